// round 3
// baseline (speedup 1.0000x reference)
#include <cuda_runtime.h>
#include <cstdint>
#include <math.h>

// Problem dims
#define BB   512
#define HH   512
#define EED  512
#define VV   2048
#define LEN  32
#define KIN  1024
#define LP1  33

// Output layout (flattened tuple: seq, probs, logp, ent — all as float32)
#define SEQ_OFF   0
#define PROBS_OFF (512*33)                       // 16896
#define LOGP_OFF  (PROBS_OFF + 512*33*2048)      // 34619904
#define ENT_OFF   (LOGP_OFF + 512*33)            // 34636800

// Persistent device scratch (no allocations allowed)
__device__ float g_hA[BB*HH];
__device__ float g_hB[BB*HH];
__device__ float g_c [BB*HH];
__device__ float g_e [BB*EED];
__device__ float g_z [BB*VV];

// ---------------------------------------------------------------------------
// Threefry2x32 (exact JAX constants/rounds)
// ---------------------------------------------------------------------------
__device__ __forceinline__ void tf2x32(uint32_t k0, uint32_t k1,
                                       uint32_t x0, uint32_t x1,
                                       uint32_t& o0, uint32_t& o1) {
  uint32_t ks2 = k0 ^ k1 ^ 0x1BD11BDAu;
#define TF_ROT(x,r) (((x) << (r)) | ((x) >> (32 - (r))))
#define TF_RND(r) { x0 += x1; x1 = TF_ROT(x1, r); x1 ^= x0; }
  x0 += k0; x1 += k1;
  TF_RND(13) TF_RND(15) TF_RND(26) TF_RND(6)   x0 += k1;  x1 += ks2 + 1u;
  TF_RND(17) TF_RND(29) TF_RND(16) TF_RND(24)  x0 += ks2; x1 += k0 + 2u;
  TF_RND(13) TF_RND(15) TF_RND(26) TF_RND(6)   x0 += k0;  x1 += k1 + 3u;
  TF_RND(17) TF_RND(29) TF_RND(16) TF_RND(24)  x0 += k1;  x1 += ks2 + 4u;
  TF_RND(13) TF_RND(15) TF_RND(26) TF_RND(6)   x0 += ks2; x1 += k0 + 5u;
  o0 = x0; o1 = x1;
#undef TF_RND
#undef TF_ROT
}

__device__ __forceinline__ float sigf(float x) { return 1.0f / (1.0f + expf(-x)); }

// ---------------------------------------------------------------------------
// Generic tiled SGEMM body: C[M,N] = A[M,K] @ W[K,N] + bias, BM=64, BK=16.
// 256 threads, thread tile 4 x (BN/16).
// ---------------------------------------------------------------------------
template<int BN>
__device__ __forceinline__ void gemm_body(const float* __restrict__ A,
                                          const float* __restrict__ W,
                                          const float* __restrict__ bias,
                                          float* __restrict__ C,
                                          int N, int K) {
  constexpr int TN = BN / 16;
  __shared__ float As[64][17];
  __shared__ float Ws[16][BN];
  const int tid = threadIdx.x;
  const int tx = tid & 15, ty = tid >> 4;
  const int m0 = blockIdx.y * 64;
  const int n0 = blockIdx.x * BN;

  float acc[4][TN];
#pragma unroll
  for (int r = 0; r < 4; r++)
#pragma unroll
    for (int c = 0; c < TN; c++) acc[r][c] = 0.0f;

  for (int kb = 0; kb < K; kb += 16) {
#pragma unroll
    for (int i = 0; i < 4; i++) {
      int idx = tid + i * 256;                // 64*16 elements
      int m = idx >> 4, k = idx & 15;
      As[m][k] = A[(size_t)(m0 + m) * K + kb + k];
    }
#pragma unroll
    for (int i = 0; i < BN / 16; i++) {       // 16*BN elements
      int idx = tid + i * 256;
      int k = idx / BN, n = idx % BN;
      Ws[k][n] = W[(size_t)(kb + k) * N + n0 + n];
    }
    __syncthreads();
#pragma unroll
    for (int k = 0; k < 16; k++) {
      float a[4], w[TN];
#pragma unroll
      for (int r = 0; r < 4; r++) a[r] = As[ty * 4 + r][k];
#pragma unroll
      for (int c = 0; c < TN; c++) w[c] = Ws[k][tx * TN + c];
#pragma unroll
      for (int r = 0; r < 4; r++)
#pragma unroll
        for (int c = 0; c < TN; c++) acc[r][c] = fmaf(a[r], w[c], acc[r][c]);
    }
    __syncthreads();
  }

#pragma unroll
  for (int r = 0; r < 4; r++) {
    int row = m0 + ty * 4 + r;
#pragma unroll
    for (int c = 0; c < TN; c++) {
      int col = n0 + tx * TN + c;
      C[(size_t)row * N + col] = acc[r][c] + bias[col];
    }
  }
}

// h0 = x @ agent_w + agent_b  -> g_hA    (M=512, N=512, K=1024)
__global__ __launch_bounds__(256) void k_h0(const float* __restrict__ x,
                                            const float* __restrict__ aw,
                                            const float* __restrict__ ab) {
  gemm_body<64>(x, aw, ab, g_hA, 512, 1024);
}

// logits = h @ out_w + out_b -> g_z      (M=512, N=2048, K=512)
__global__ __launch_bounds__(256) void k_logits(const float* __restrict__ ow,
                                                const float* __restrict__ ob,
                                                int p) {
  const float* h = p ? g_hA : g_hB;  // h_out of step t = (t&1) ? g_hA : g_hB
  gemm_body<128>(h, ow, ob, g_z, 2048, 512);
}

// ---------------------------------------------------------------------------
// Fused gates GEMM + LSTM pointwise.
// gates = e @ w_ih + h @ w_hh + (b_ih + b_hh), gate order i,f,g,o (torch).
// Block computes 64 batch rows x 32 hidden cols across all 4 gates (cols
// n0+c, n0+c+512, n0+c+1024, n0+c+1536), then updates c,h in place/ping-pong.
// ---------------------------------------------------------------------------
__global__ __launch_bounds__(256) void k_gates(const float* __restrict__ w_ih,
                                               const float* __restrict__ w_hh,
                                               const float* __restrict__ b_ih,
                                               const float* __restrict__ b_hh,
                                               int p) {
  const float* __restrict__ h_in  = p ? g_hB : g_hA;
  float*       __restrict__ h_out = p ? g_hA : g_hB;

  __shared__ float As[64][17];
  __shared__ float Ws[16][128];
  const int tid = threadIdx.x;
  const int tx = tid & 15, ty = tid >> 4;
  const int m0 = blockIdx.y * 64;   // batch rows
  const int n0 = blockIdx.x * 32;   // per-gate hidden cols

  float acc[4][4][2];               // [gate][row][col]
#pragma unroll
  for (int g = 0; g < 4; g++)
#pragma unroll
    for (int r = 0; r < 4; r++) { acc[g][r][0] = 0.f; acc[g][r][1] = 0.f; }

  for (int kb = 0; kb < 1024; kb += 16) {
    const float* __restrict__ Asrc = (kb < 512) ? g_e : h_in;
    const float* __restrict__ Wsrc = (kb < 512) ? w_ih : w_hh;
    const int kl = kb & 511;
#pragma unroll
    for (int i = 0; i < 4; i++) {
      int idx = tid + i * 256;
      int m = idx >> 4, k = idx & 15;
      As[m][k] = Asrc[(size_t)(m0 + m) * 512 + kl + k];
    }
#pragma unroll
    for (int i = 0; i < 8; i++) {
      int idx = tid + i * 256;
      int k = idx >> 7, n = idx & 127;
      int g = n >> 5, c = n & 31;
      Ws[k][n] = Wsrc[(size_t)(kl + k) * 2048 + g * 512 + n0 + c];
    }
    __syncthreads();
#pragma unroll
    for (int k = 0; k < 16; k++) {
      float a[4];
#pragma unroll
      for (int r = 0; r < 4; r++) a[r] = As[ty * 4 + r][k];
      float w[4][2];
#pragma unroll
      for (int g = 0; g < 4; g++) {
        w[g][0] = Ws[k][g * 32 + tx * 2];
        w[g][1] = Ws[k][g * 32 + tx * 2 + 1];
      }
#pragma unroll
      for (int g = 0; g < 4; g++)
#pragma unroll
        for (int r = 0; r < 4; r++) {
          acc[g][r][0] = fmaf(a[r], w[g][0], acc[g][r][0]);
          acc[g][r][1] = fmaf(a[r], w[g][1], acc[g][r][1]);
        }
    }
    __syncthreads();
  }

#pragma unroll
  for (int r = 0; r < 4; r++) {
    int row = m0 + ty * 4 + r;
#pragma unroll
    for (int c = 0; c < 2; c++) {
      int col = n0 + tx * 2 + c;
      float ig = acc[0][r][c] + b_ih[col]        + b_hh[col];
      float fg = acc[1][r][c] + b_ih[512 + col]  + b_hh[512 + col];
      float gg = acc[2][r][c] + b_ih[1024 + col] + b_hh[1024 + col];
      float og = acc[3][r][c] + b_ih[1536 + col] + b_hh[1536 + col];
      int off = row * 512 + col;
      float cv = g_c[off];
      float cn = sigf(fg) * cv + sigf(ig) * tanhf(gg);
      float hn = sigf(og) * tanhf(cn);
      g_c[off]  = cn;
      h_out[off] = hn;
    }
  }
}

// ---------------------------------------------------------------------------
// Per-row: log-softmax, probs/entropy outputs, Gumbel-argmax sample (JAX
// partitionable threefry), log_prob gather, embedding lookup into g_e.
// One block per batch row, 256 threads (each owns 8 of V=2048 columns).
// ---------------------------------------------------------------------------
__global__ __launch_bounds__(256) void k_sample(const float* __restrict__ emb,
                                                float* __restrict__ out,
                                                int t) {
  const int b = blockIdx.x;
  const int tid = threadIdx.x;
  const float* __restrict__ z = g_z + (size_t)b * VV;

  float zv[8];
#pragma unroll
  for (int j = 0; j < 8; j++) zv[j] = z[tid + j * 256];

  __shared__ float red[256];
  __shared__ float rv[256];
  __shared__ int   ri[256];
  __shared__ int   s_sym;

  // max
  float m = zv[0];
#pragma unroll
  for (int j = 1; j < 8; j++) m = fmaxf(m, zv[j]);
  red[tid] = m; __syncthreads();
  for (int s = 128; s > 0; s >>= 1) {
    if (tid < s) red[tid] = fmaxf(red[tid], red[tid + s]);
    __syncthreads();
  }
  const float M = red[0]; __syncthreads();

  // logsumexp
  float ssum = 0.f;
#pragma unroll
  for (int j = 0; j < 8; j++) ssum += expf(zv[j] - M);
  red[tid] = ssum; __syncthreads();
  for (int s = 128; s > 0; s >>= 1) {
    if (tid < s) red[tid] += red[tid + s];
    __syncthreads();
  }
  const float lse = logf(red[0]); __syncthreads();

  // JAX key chain: key0 = key(1) = (0,1); per step (fold-like split,
  // partitionable default): new_key = tf(key,(0,0)), subkey = tf(key,(0,1)).
  uint32_t k0 = 0u, k1 = 1u, sk0 = 0u, sk1 = 0u;
  for (int st = 0; st <= t; st++) {
    uint32_t n0, n1, s0, s1;
    tf2x32(k0, k1, 0u, 0u, n0, n1);
    tf2x32(k0, k1, 0u, 1u, s0, s1);
    sk0 = s0; sk1 = s1; k0 = n0; k1 = n1;
  }

  float entp = 0.f;
  float bestv = -INFINITY;
  int   besti = VV;
  const size_t probs_row = (size_t)PROBS_OFF + ((size_t)b * LP1 + t) * VV;
#pragma unroll
  for (int j = 0; j < 8; j++) {
    int v = tid + j * 256;
    float lsm = zv[j] - M - lse;
    float pr = expf(lsm);
    out[probs_row + v] = pr;
    entp += pr * lsm;

    // partitionable random_bits: counter = flat index (hi=0), bits = o0^o1
    uint32_t o0, o1;
    tf2x32(sk0, sk1, 0u, (uint32_t)(b * VV + v), o0, o1);
    uint32_t bits = o0 ^ o1;
    float f = __uint_as_float((bits >> 9) | 0x3f800000u) - 1.0f;
    float u = fmaxf(f, 1.1754943508222875e-38f);  // minval = tiny
    float gum = -logf(-logf(u));
    float val = gum + lsm;
    if (val > bestv || (val == bestv && v < besti)) { bestv = val; besti = v; }
  }

  // entropy sum
  red[tid] = entp; __syncthreads();
  for (int s = 128; s > 0; s >>= 1) {
    if (tid < s) red[tid] += red[tid + s];
    __syncthreads();
  }
  const float ENT = red[0]; __syncthreads();

  // argmax (first index on ties)
  rv[tid] = bestv; ri[tid] = besti; __syncthreads();
  for (int s = 128; s > 0; s >>= 1) {
    if (tid < s) {
      if (rv[tid + s] > rv[tid] ||
          (rv[tid + s] == rv[tid] && ri[tid + s] < ri[tid])) {
        rv[tid] = rv[tid + s]; ri[tid] = ri[tid + s];
      }
    }
    __syncthreads();
  }
  if (tid == 0) {
    int sym = ri[0];
    s_sym = sym;
    float lsm_s = z[sym] - M - lse;
    out[SEQ_OFF  + b * LP1 + t] = (float)sym;
    out[LOGP_OFF + b * LP1 + t] = lsm_s;
    out[ENT_OFF  + b * LP1 + t] = -ENT;
  }
  __syncthreads();
  const int sym = s_sym;
  // next-step embedding
  g_e[b * EED + tid]       = emb[(size_t)sym * EED + tid];
  g_e[b * EED + 256 + tid] = emb[(size_t)sym * EED + 256 + tid];
}

// ---------------------------------------------------------------------------
// Init: EOS column outputs, e = sos broadcast, c = 0.
// ---------------------------------------------------------------------------
__global__ __launch_bounds__(256) void k_init(const float* __restrict__ sos,
                                              float* __restrict__ out) {
  int idx = blockIdx.x * 256 + threadIdx.x;   // 512*2048 threads total
  int b = idx >> 11, v = idx & 2047;
  out[(size_t)PROBS_OFF + ((size_t)b * LP1 + LEN) * VV + v] = 1.0f;
  if (v < 512) {
    g_e[b * EED + v] = sos[v];
    g_c[b * HH + v] = 0.0f;
  }
  if (v == 0) {
    out[SEQ_OFF  + b * LP1 + LEN] = 0.0f;
    out[LOGP_OFF + b * LP1 + LEN] = 0.0f;
    out[ENT_OFF  + b * LP1 + LEN] = 0.0f;
  }
}

// ---------------------------------------------------------------------------
extern "C" void kernel_launch(void* const* d_in, const int* in_sizes, int n_in,
                              void* d_out, int out_size) {
  const float* x       = (const float*)d_in[0];
  const float* agent_w = (const float*)d_in[1];
  const float* agent_b = (const float*)d_in[2];
  const float* sos     = (const float*)d_in[3];
  const float* emb     = (const float*)d_in[4];
  const float* w_ih    = (const float*)d_in[5];
  const float* w_hh    = (const float*)d_in[6];
  const float* b_ih    = (const float*)d_in[7];
  const float* b_hh    = (const float*)d_in[8];
  const float* out_w   = (const float*)d_in[9];
  const float* out_b   = (const float*)d_in[10];
  float* out = (float*)d_out;

  k_init<<<4096, 256>>>(sos, out);
  k_h0<<<dim3(8, 8), 256>>>(x, agent_w, agent_b);

  for (int t = 0; t < LEN; t++) {
    int p = t & 1;
    k_gates<<<dim3(16, 8), 256>>>(w_ih, w_hh, b_ih, b_hh, p);
    k_logits<<<dim3(16, 8), 256>>>(out_w, out_b, p);
    k_sample<<<512, 256>>>(emb, out, t);
  }
}

// round 4
// speedup vs baseline: 1.0015x; 1.0015x over previous
#include <cuda_runtime.h>
#include <cstdint>
#include <math.h>

// Problem dims
#define BB   512
#define HH   512
#define EED  512
#define VV   2048
#define LEN  32
#define KIN  1024
#define LP1  33

// Output layout (flattened tuple: seq, probs, logp, ent — all as float32)
#define SEQ_OFF   0
#define PROBS_OFF (512*33)                       // 16896
#define LOGP_OFF  (PROBS_OFF + 512*33*2048)      // 34619904
#define ENT_OFF   (LOGP_OFF + 512*33)            // 34636800

// Persistent device scratch (no allocations allowed)
__device__ float g_hA[BB*HH];
__device__ float g_hB[BB*HH];
__device__ float g_c [BB*HH];
__device__ float g_e [BB*EED];
__device__ float g_z [BB*VV];

// ---------------------------------------------------------------------------
// Threefry2x32 (exact JAX constants/rounds)
// ---------------------------------------------------------------------------
__device__ __forceinline__ void tf2x32(uint32_t k0, uint32_t k1,
                                       uint32_t x0, uint32_t x1,
                                       uint32_t& o0, uint32_t& o1) {
  uint32_t ks2 = k0 ^ k1 ^ 0x1BD11BDAu;
#define TF_ROT(x,r) (((x) << (r)) | ((x) >> (32 - (r))))
#define TF_RND(r) { x0 += x1; x1 = TF_ROT(x1, r); x1 ^= x0; }
  x0 += k0; x1 += k1;
  TF_RND(13) TF_RND(15) TF_RND(26) TF_RND(6)   x0 += k1;  x1 += ks2 + 1u;
  TF_RND(17) TF_RND(29) TF_RND(16) TF_RND(24)  x0 += ks2; x1 += k0 + 2u;
  TF_RND(13) TF_RND(15) TF_RND(26) TF_RND(6)   x0 += k0;  x1 += k1 + 3u;
  TF_RND(17) TF_RND(29) TF_RND(16) TF_RND(24)  x0 += k1;  x1 += ks2 + 4u;
  TF_RND(13) TF_RND(15) TF_RND(26) TF_RND(6)   x0 += ks2; x1 += k0 + 5u;
  o0 = x0; o1 = x1;
#undef TF_RND
#undef TF_ROT
}

__device__ __forceinline__ float sigf(float x) { return 1.0f / (1.0f + expf(-x)); }

// ---------------------------------------------------------------------------
// Generic tiled SGEMM body: C[M,N] = A[M,K] @ W[K,N] + bias, BM=64, BK=16.
// 256 threads, thread tile 4 x (BN/16).
// ---------------------------------------------------------------------------
template<int BN>
__device__ __forceinline__ void gemm_body(const float* __restrict__ A,
                                          const float* __restrict__ W,
                                          const float* __restrict__ bias,
                                          float* __restrict__ C,
                                          int N, int K) {
  constexpr int TN = BN / 16;
  __shared__ float As[64][17];
  __shared__ float Ws[16][BN];
  const int tid = threadIdx.x;
  const int tx = tid & 15, ty = tid >> 4;
  const int m0 = blockIdx.y * 64;
  const int n0 = blockIdx.x * BN;

  float acc[4][TN];
#pragma unroll
  for (int r = 0; r < 4; r++)
#pragma unroll
    for (int c = 0; c < TN; c++) acc[r][c] = 0.0f;

  for (int kb = 0; kb < K; kb += 16) {
#pragma unroll
    for (int i = 0; i < 4; i++) {
      int idx = tid + i * 256;                // 64*16 elements
      int m = idx >> 4, k = idx & 15;
      As[m][k] = A[(size_t)(m0 + m) * K + kb + k];
    }
#pragma unroll
    for (int i = 0; i < BN / 16; i++) {       // 16*BN elements
      int idx = tid + i * 256;
      int k = idx / BN, n = idx % BN;
      Ws[k][n] = W[(size_t)(kb + k) * N + n0 + n];
    }
    __syncthreads();
#pragma unroll
    for (int k = 0; k < 16; k++) {
      float a[4], w[TN];
#pragma unroll
      for (int r = 0; r < 4; r++) a[r] = As[ty * 4 + r][k];
#pragma unroll
      for (int c = 0; c < TN; c++) w[c] = Ws[k][tx * TN + c];
#pragma unroll
      for (int r = 0; r < 4; r++)
#pragma unroll
        for (int c = 0; c < TN; c++) acc[r][c] = fmaf(a[r], w[c], acc[r][c]);
    }
    __syncthreads();
  }

#pragma unroll
  for (int r = 0; r < 4; r++) {
    int row = m0 + ty * 4 + r;
#pragma unroll
    for (int c = 0; c < TN; c++) {
      int col = n0 + tx * TN + c;
      C[(size_t)row * N + col] = acc[r][c] + bias[col];
    }
  }
}

// h0 = x @ agent_w + agent_b  -> g_hA    (M=512, N=512, K=1024)
__global__ __launch_bounds__(256) void k_h0(const float* __restrict__ x,
                                            const float* __restrict__ aw,
                                            const float* __restrict__ ab) {
  gemm_body<64>(x, aw, ab, g_hA, 512, 1024);
}

// logits = h @ out_w + out_b -> g_z      (M=512, N=2048, K=512)
__global__ __launch_bounds__(256) void k_logits(const float* __restrict__ ow,
                                                const float* __restrict__ ob,
                                                int p) {
  const float* h = p ? g_hA : g_hB;  // h_out of step t = (t&1) ? g_hA : g_hB
  gemm_body<128>(h, ow, ob, g_z, 2048, 512);
}

// ---------------------------------------------------------------------------
// Fused gates GEMM + LSTM pointwise.
// gates = e @ w_ih + h @ w_hh + (b_ih + b_hh), gate order i,f,g,o (torch).
// Block computes 64 batch rows x 32 hidden cols across all 4 gates (cols
// n0+c, n0+c+512, n0+c+1024, n0+c+1536), then updates c,h in place/ping-pong.
// ---------------------------------------------------------------------------
__global__ __launch_bounds__(256) void k_gates(const float* __restrict__ w_ih,
                                               const float* __restrict__ w_hh,
                                               const float* __restrict__ b_ih,
                                               const float* __restrict__ b_hh,
                                               int p) {
  const float* __restrict__ h_in  = p ? g_hB : g_hA;
  float*       __restrict__ h_out = p ? g_hA : g_hB;

  __shared__ float As[64][17];
  __shared__ float Ws[16][128];
  const int tid = threadIdx.x;
  const int tx = tid & 15, ty = tid >> 4;
  const int m0 = blockIdx.y * 64;   // batch rows
  const int n0 = blockIdx.x * 32;   // per-gate hidden cols

  float acc[4][4][2];               // [gate][row][col]
#pragma unroll
  for (int g = 0; g < 4; g++)
#pragma unroll
    for (int r = 0; r < 4; r++) { acc[g][r][0] = 0.f; acc[g][r][1] = 0.f; }

  for (int kb = 0; kb < 1024; kb += 16) {
    const float* __restrict__ Asrc = (kb < 512) ? g_e : h_in;
    const float* __restrict__ Wsrc = (kb < 512) ? w_ih : w_hh;
    const int kl = kb & 511;
#pragma unroll
    for (int i = 0; i < 4; i++) {
      int idx = tid + i * 256;
      int m = idx >> 4, k = idx & 15;
      As[m][k] = Asrc[(size_t)(m0 + m) * 512 + kl + k];
    }
#pragma unroll
    for (int i = 0; i < 8; i++) {
      int idx = tid + i * 256;
      int k = idx >> 7, n = idx & 127;
      int g = n >> 5, c = n & 31;
      Ws[k][n] = Wsrc[(size_t)(kl + k) * 2048 + g * 512 + n0 + c];
    }
    __syncthreads();
#pragma unroll
    for (int k = 0; k < 16; k++) {
      float a[4];
#pragma unroll
      for (int r = 0; r < 4; r++) a[r] = As[ty * 4 + r][k];
      float w[4][2];
#pragma unroll
      for (int g = 0; g < 4; g++) {
        w[g][0] = Ws[k][g * 32 + tx * 2];
        w[g][1] = Ws[k][g * 32 + tx * 2 + 1];
      }
#pragma unroll
      for (int g = 0; g < 4; g++)
#pragma unroll
        for (int r = 0; r < 4; r++) {
          acc[g][r][0] = fmaf(a[r], w[g][0], acc[g][r][0]);
          acc[g][r][1] = fmaf(a[r], w[g][1], acc[g][r][1]);
        }
    }
    __syncthreads();
  }

#pragma unroll
  for (int r = 0; r < 4; r++) {
    int row = m0 + ty * 4 + r;
#pragma unroll
    for (int c = 0; c < 2; c++) {
      int col = n0 + tx * 2 + c;
      float ig = acc[0][r][c] + b_ih[col]        + b_hh[col];
      float fg = acc[1][r][c] + b_ih[512 + col]  + b_hh[512 + col];
      float gg = acc[2][r][c] + b_ih[1024 + col] + b_hh[1024 + col];
      float og = acc[3][r][c] + b_ih[1536 + col] + b_hh[1536 + col];
      int off = row * 512 + col;
      float cv = g_c[off];
      float cn = sigf(fg) * cv + sigf(ig) * tanhf(gg);
      float hn = sigf(og) * tanhf(cn);
      g_c[off]  = cn;
      h_out[off] = hn;
    }
  }
}

// ---------------------------------------------------------------------------
// Per-row: log-softmax, probs/entropy outputs, Gumbel-argmax sample (JAX
// partitionable threefry), log_prob gather, embedding lookup into g_e.
// One block per batch row, 256 threads (each owns 8 of V=2048 columns).
// ---------------------------------------------------------------------------
__global__ __launch_bounds__(256) void k_sample(const float* __restrict__ emb,
                                                float* __restrict__ out,
                                                int t) {
  const int b = blockIdx.x;
  const int tid = threadIdx.x;
  const float* __restrict__ z = g_z + (size_t)b * VV;

  float zv[8];
#pragma unroll
  for (int j = 0; j < 8; j++) zv[j] = z[tid + j * 256];

  __shared__ float red[256];
  __shared__ float rv[256];
  __shared__ int   ri[256];
  __shared__ int   s_sym;

  // max
  float m = zv[0];
#pragma unroll
  for (int j = 1; j < 8; j++) m = fmaxf(m, zv[j]);
  red[tid] = m; __syncthreads();
  for (int s = 128; s > 0; s >>= 1) {
    if (tid < s) red[tid] = fmaxf(red[tid], red[tid + s]);
    __syncthreads();
  }
  const float M = red[0]; __syncthreads();

  // logsumexp
  float ssum = 0.f;
#pragma unroll
  for (int j = 0; j < 8; j++) ssum += expf(zv[j] - M);
  red[tid] = ssum; __syncthreads();
  for (int s = 128; s > 0; s >>= 1) {
    if (tid < s) red[tid] += red[tid + s];
    __syncthreads();
  }
  const float lse = logf(red[0]); __syncthreads();

  // JAX key chain: key0 = key(1) = (0,1); per step (fold-like split,
  // partitionable default): new_key = tf(key,(0,0)), subkey = tf(key,(0,1)).
  uint32_t k0 = 0u, k1 = 1u, sk0 = 0u, sk1 = 0u;
  for (int st = 0; st <= t; st++) {
    uint32_t n0, n1, s0, s1;
    tf2x32(k0, k1, 0u, 0u, n0, n1);
    tf2x32(k0, k1, 0u, 1u, s0, s1);
    sk0 = s0; sk1 = s1; k0 = n0; k1 = n1;
  }

  float entp = 0.f;
  float bestv = -INFINITY;
  int   besti = VV;
  const size_t probs_row = (size_t)PROBS_OFF + ((size_t)b * LP1 + t) * VV;
#pragma unroll
  for (int j = 0; j < 8; j++) {
    int v = tid + j * 256;
    float lsm = zv[j] - M - lse;
    float pr = expf(lsm);
    out[probs_row + v] = pr;
    entp += pr * lsm;

    // partitionable random_bits: counter = flat index (hi=0), bits = o0^o1
    uint32_t o0, o1;
    tf2x32(sk0, sk1, 0u, (uint32_t)(b * VV + v), o0, o1);
    uint32_t bits = o0 ^ o1;
    float f = __uint_as_float((bits >> 9) | 0x3f800000u) - 1.0f;
    float u = fmaxf(f, 1.1754943508222875e-38f);  // minval = tiny
    float gum = -logf(-logf(u));
    float val = gum + lsm;
    if (val > bestv || (val == bestv && v < besti)) { bestv = val; besti = v; }
  }

  // entropy sum
  red[tid] = entp; __syncthreads();
  for (int s = 128; s > 0; s >>= 1) {
    if (tid < s) red[tid] += red[tid + s];
    __syncthreads();
  }
  const float ENT = red[0]; __syncthreads();

  // argmax (first index on ties)
  rv[tid] = bestv; ri[tid] = besti; __syncthreads();
  for (int s = 128; s > 0; s >>= 1) {
    if (tid < s) {
      if (rv[tid + s] > rv[tid] ||
          (rv[tid + s] == rv[tid] && ri[tid + s] < ri[tid])) {
        rv[tid] = rv[tid + s]; ri[tid] = ri[tid + s];
      }
    }
    __syncthreads();
  }
  if (tid == 0) {
    int sym = ri[0];
    s_sym = sym;
    float lsm_s = z[sym] - M - lse;
    out[SEQ_OFF  + b * LP1 + t] = (float)sym;
    out[LOGP_OFF + b * LP1 + t] = lsm_s;
    out[ENT_OFF  + b * LP1 + t] = -ENT;
  }
  __syncthreads();
  const int sym = s_sym;
  // next-step embedding
  g_e[b * EED + tid]       = emb[(size_t)sym * EED + tid];
  g_e[b * EED + 256 + tid] = emb[(size_t)sym * EED + 256 + tid];
}

// ---------------------------------------------------------------------------
// Init: EOS column outputs, e = sos broadcast, c = 0.
// ---------------------------------------------------------------------------
__global__ __launch_bounds__(256) void k_init(const float* __restrict__ sos,
                                              float* __restrict__ out) {
  int idx = blockIdx.x * 256 + threadIdx.x;   // 512*2048 threads total
  int b = idx >> 11, v = idx & 2047;
  out[(size_t)PROBS_OFF + ((size_t)b * LP1 + LEN) * VV + v] = 1.0f;
  if (v < 512) {
    g_e[b * EED + v] = sos[v];
    g_c[b * HH + v] = 0.0f;
  }
  if (v == 0) {
    out[SEQ_OFF  + b * LP1 + LEN] = 0.0f;
    out[LOGP_OFF + b * LP1 + LEN] = 0.0f;
    out[ENT_OFF  + b * LP1 + LEN] = 0.0f;
  }
}

// ---------------------------------------------------------------------------
extern "C" void kernel_launch(void* const* d_in, const int* in_sizes, int n_in,
                              void* d_out, int out_size) {
  const float* x       = (const float*)d_in[0];
  const float* agent_w = (const float*)d_in[1];
  const float* agent_b = (const float*)d_in[2];
  const float* sos     = (const float*)d_in[3];
  const float* emb     = (const float*)d_in[4];
  const float* w_ih    = (const float*)d_in[5];
  const float* w_hh    = (const float*)d_in[6];
  const float* b_ih    = (const float*)d_in[7];
  const float* b_hh    = (const float*)d_in[8];
  const float* out_w   = (const float*)d_in[9];
  const float* out_b   = (const float*)d_in[10];
  float* out = (float*)d_out;

  k_init<<<4096, 256>>>(sos, out);
  k_h0<<<dim3(8, 8), 256>>>(x, agent_w, agent_b);

  for (int t = 0; t < LEN; t++) {
    int p = t & 1;
    k_gates<<<dim3(16, 8), 256>>>(w_ih, w_hh, b_ih, b_hh, p);
    k_logits<<<dim3(16, 8), 256>>>(out_w, out_b, p);
    k_sample<<<512, 256>>>(emb, out, t);
  }
}

// round 6
// speedup vs baseline: 1.2634x; 1.2615x over previous
#include <cuda_runtime.h>
#include <cuda_bf16.h>
#include <cstdint>
#include <math.h>

#define VV 2048
#define LP1 33
#define SEQ_OFF   0
#define PROBS_OFF (512*33)
#define LOGP_OFF  (PROBS_OFF + 512*33*2048)
#define ENT_OFF   (LOGP_OFF + 512*33)

// 6-product split schedule: segment s uses A-plane PI[s], B-plane PJ[s]
// pairs: (0,0) (0,1) (1,0) (0,2) (2,0) (1,1)  == hh hm mh hl lh mm
// PI = {0,0,1,0,2,1}  -> plane0 segs {0,1,3}, plane1 {2,5}, plane2 {4}
// PJ = {0,1,0,2,0,1}  -> plane0 segs {0,2,4}, plane1 {1,5}, plane2 {3}

// ---------------------------------------------------------------------------
// Persistent device scratch (no runtime allocations allowed)
// ---------------------------------------------------------------------------
__device__ __nv_bfloat16 g_Wg[2048 * 6144];  // gates weights, [new_n][k'=6*1024]
__device__ __nv_bfloat16 g_Wo[2048 * 3072];  // out_w,        [n][k'=6*512]
__device__ __nv_bfloat16 g_E6[2048 * 3072];  // embedding,    [v][6*512] (PI order)
__device__ __nv_bfloat16 g_Ag[512 * 6144];   // gates A: seg p = [e_PI[p] | h_PI[p]]
__device__ __nv_bfloat16 g_Al[512 * 3072];   // logits A: seg p = h_PI[p]
__device__ float g_part[2][512 * 2048];      // split-K partials (shared gates/logits)
__device__ float g_c  [512 * 512];
__device__ float g_h0f[512 * 512];

// ---------------------------------------------------------------------------
__device__ __forceinline__ uint32_t smem_to_u32(const void* p) {
  uint32_t a;
  asm("{ .reg .u64 t; cvta.to.shared.u64 t, %1; cvt.u32.u64 %0, t; }"
      : "=r"(a) : "l"(p));
  return a;
}

__device__ __forceinline__ void split3(float f, __nv_bfloat16& b0,
                                       __nv_bfloat16& b1, __nv_bfloat16& b2) {
  b0 = __float2bfloat16(f);
  float r1 = f - __bfloat162float(b0);
  b1 = __float2bfloat16(r1);
  float r2 = r1 - __bfloat162float(b1);
  b2 = __float2bfloat16(r2);
}

// Threefry2x32 (exact JAX constants)
__device__ __forceinline__ void tf2x32(uint32_t k0, uint32_t k1,
                                       uint32_t x0, uint32_t x1,
                                       uint32_t& o0, uint32_t& o1) {
  uint32_t ks2 = k0 ^ k1 ^ 0x1BD11BDAu;
#define TF_ROT(x,r) (((x) << (r)) | ((x) >> (32 - (r))))
#define TF_RND(r) { x0 += x1; x1 = TF_ROT(x1, r); x1 ^= x0; }
  x0 += k0; x1 += k1;
  TF_RND(13) TF_RND(15) TF_RND(26) TF_RND(6)   x0 += k1;  x1 += ks2 + 1u;
  TF_RND(17) TF_RND(29) TF_RND(16) TF_RND(24)  x0 += ks2; x1 += k0 + 2u;
  TF_RND(13) TF_RND(15) TF_RND(26) TF_RND(6)   x0 += k0;  x1 += k1 + 3u;
  TF_RND(17) TF_RND(29) TF_RND(16) TF_RND(24)  x0 += k1;  x1 += ks2 + 4u;
  TF_RND(13) TF_RND(15) TF_RND(26) TF_RND(6)   x0 += ks2; x1 += k0 + 5u;
  o0 = x0; o1 = x1;
#undef TF_RND
#undef TF_ROT
}

__device__ __forceinline__ float sigf(float x) { return 1.0f / (1.0f + expf(-x)); }

// ---------------------------------------------------------------------------
// Setup kernels (run each replay; cheap)
// ---------------------------------------------------------------------------
// gates weights: orig [k][2048] (k<512: w_ih, else w_hh) -> g_Wg[new_n][6144]
// new_n = hgroup*128 + gate*32 + hl  (orig col = gate*512 + hgroup*32 + hl)
__global__ __launch_bounds__(256) void k_split_wg(const float* __restrict__ w_ih,
                                                  const float* __restrict__ w_hh) {
  __shared__ float t[32][33];
  const int nt = blockIdx.x, kt = blockIdx.y;     // nt<64, kt<32
  const int tx = threadIdx.x & 31, ty = threadIdx.x >> 5;
  const int gate = nt & 3;
  const int orig = gate * 512 + ((nt >> 2) << 5) + tx;
#pragma unroll
  for (int r = 0; r < 4; r++) {
    int kl = ty + r * 8;
    int k = kt * 32 + kl;
    t[kl][tx] = (k < 512) ? w_ih[(size_t)k * 2048 + orig]
                          : w_hh[(size_t)(k - 512) * 2048 + orig];
  }
  __syncthreads();
#pragma unroll
  for (int r = 0; r < 4; r++) {
    int nl = ty + r * 8;
    float f = t[tx][nl];
    __nv_bfloat16 b0, b1, b2; split3(f, b0, b1, b2);
    size_t base = (size_t)(nt * 32 + nl) * 6144 + kt * 32 + tx;
    g_Wg[base + 0 * 1024] = b0;  // PJ segs for plane0: 0,2,4
    g_Wg[base + 2 * 1024] = b0;
    g_Wg[base + 4 * 1024] = b0;
    g_Wg[base + 1 * 1024] = b1;  // plane1: 1,5
    g_Wg[base + 5 * 1024] = b1;
    g_Wg[base + 3 * 1024] = b2;  // plane2: 3
  }
}

// out_w: [k=512][2048] -> g_Wo[n][3072]
__global__ __launch_bounds__(256) void k_split_wo(const float* __restrict__ ow) {
  __shared__ float t[32][33];
  const int nt = blockIdx.x, kt = blockIdx.y;     // nt<64, kt<16
  const int tx = threadIdx.x & 31, ty = threadIdx.x >> 5;
#pragma unroll
  for (int r = 0; r < 4; r++) {
    int kl = ty + r * 8;
    t[kl][tx] = ow[(size_t)(kt * 32 + kl) * 2048 + nt * 32 + tx];
  }
  __syncthreads();
#pragma unroll
  for (int r = 0; r < 4; r++) {
    int nl = ty + r * 8;
    float f = t[tx][nl];
    __nv_bfloat16 b0, b1, b2; split3(f, b0, b1, b2);
    size_t base = (size_t)(nt * 32 + nl) * 3072 + kt * 32 + tx;
    g_Wo[base + 0 * 512] = b0;
    g_Wo[base + 2 * 512] = b0;
    g_Wo[base + 4 * 512] = b0;
    g_Wo[base + 1 * 512] = b1;
    g_Wo[base + 5 * 512] = b1;
    g_Wo[base + 3 * 512] = b2;
  }
}

__global__ __launch_bounds__(256) void k_split_emb(const float* __restrict__ emb) {
  int idx = blockIdx.x * 256 + threadIdx.x;       // 2048*512
  int v = idx >> 9, c = idx & 511;
  __nv_bfloat16 b0, b1, b2; split3(emb[idx], b0, b1, b2);
  size_t base = (size_t)v * 3072 + c;
  g_E6[base + 0 * 512] = b0;   // PI segs plane0: 0,1,3
  g_E6[base + 1 * 512] = b0;
  g_E6[base + 3 * 512] = b0;
  g_E6[base + 2 * 512] = b1;   // plane1: 2,5
  g_E6[base + 5 * 512] = b1;
  g_E6[base + 4 * 512] = b2;   // plane2: 4
}

__global__ __launch_bounds__(256) void k_splitH0() {
  int idx = blockIdx.x * 256 + threadIdx.x;       // 512*512
  int r = idx >> 9, c = idx & 511;
  __nv_bfloat16 b0, b1, b2; split3(g_h0f[idx], b0, b1, b2);
  size_t base = (size_t)r * 6144 + 512 + c;
  g_Ag[base + 0 * 1024] = b0;
  g_Ag[base + 1 * 1024] = b0;
  g_Ag[base + 3 * 1024] = b0;
  g_Ag[base + 2 * 1024] = b1;
  g_Ag[base + 5 * 1024] = b1;
  g_Ag[base + 4 * 1024] = b2;
}

__global__ __launch_bounds__(256) void k_init(const float* __restrict__ sos,
                                              float* __restrict__ out) {
  int idx = blockIdx.x * 256 + threadIdx.x;       // 512*2048
  int b = idx >> 11, v = idx & 2047;
  out[(size_t)PROBS_OFF + ((size_t)b * LP1 + 32) * VV + v] = 1.0f;
  if (v < 512) {
    __nv_bfloat16 b0, b1, b2; split3(sos[v], b0, b1, b2);
    size_t base = (size_t)b * 6144 + v;
    g_Ag[base + 0 * 1024] = b0;
    g_Ag[base + 1 * 1024] = b0;
    g_Ag[base + 3 * 1024] = b0;
    g_Ag[base + 2 * 1024] = b1;
    g_Ag[base + 5 * 1024] = b1;
    g_Ag[base + 4 * 1024] = b2;
    g_c[b * 512 + v] = 0.0f;
  }
  if (v == 0) {
    out[SEQ_OFF  + b * LP1 + 32] = 0.0f;
    out[LOGP_OFF + b * LP1 + 32] = 0.0f;
    out[ENT_OFF  + b * LP1 + 32] = 0.0f;
  }
}

// ---------------------------------------------------------------------------
// SIMT fp32 GEMM for h0 (once): h0 = x @ agent_w + agent_b
// ---------------------------------------------------------------------------
__global__ __launch_bounds__(256) void k_h0(const float* __restrict__ A,
                                            const float* __restrict__ W,
                                            const float* __restrict__ bias) {
  const int N = 512, K = 1024;
  __shared__ float As[64][17];
  __shared__ float Ws[16][64];
  const int tid = threadIdx.x;
  const int tx = tid & 15, ty = tid >> 4;
  const int m0 = blockIdx.y * 64, n0 = blockIdx.x * 64;
  float acc[4][4];
#pragma unroll
  for (int r = 0; r < 4; r++)
#pragma unroll
    for (int c = 0; c < 4; c++) acc[r][c] = 0.f;
  for (int kb = 0; kb < K; kb += 16) {
#pragma unroll
    for (int i = 0; i < 4; i++) {
      int idx = tid + i * 256;
      As[idx >> 4][idx & 15] = A[(size_t)(m0 + (idx >> 4)) * K + kb + (idx & 15)];
    }
#pragma unroll
    for (int i = 0; i < 4; i++) {
      int idx = tid + i * 256;
      Ws[idx >> 6][idx & 63] = W[(size_t)(kb + (idx >> 6)) * N + n0 + (idx & 63)];
    }
    __syncthreads();
#pragma unroll
    for (int k = 0; k < 16; k++) {
      float a[4], w[4];
#pragma unroll
      for (int r = 0; r < 4; r++) a[r] = As[ty * 4 + r][k];
#pragma unroll
      for (int c = 0; c < 4; c++) w[c] = Ws[k][tx * 4 + c];
#pragma unroll
      for (int r = 0; r < 4; r++)
#pragma unroll
        for (int c = 0; c < 4; c++) acc[r][c] = fmaf(a[r], w[c], acc[r][c]);
    }
    __syncthreads();
  }
#pragma unroll
  for (int r = 0; r < 4; r++)
#pragma unroll
    for (int c = 0; c < 4; c++)
      g_h0f[(size_t)(m0 + ty * 4 + r) * N + n0 + tx * 4 + c] =
          acc[r][c] + bias[n0 + tx * 4 + c];
}

// ---------------------------------------------------------------------------
// bf16 HMMA GEMM: part[z] = A[M,KF] @ Bt[N,KF]^T (KF split in 2 halves)
// 128x128 tile / CTA, BK=32, 2-stage cp.async pipeline, 8 warps (2x4),
// warp tile 64x32, mma.sync m16n8k16. MODE 0: gates (KF=6144), 1: logits (3072).
// ---------------------------------------------------------------------------
#define LDM_X4(r0,r1,r2,r3,addr) \
  asm volatile("ldmatrix.sync.aligned.m8n8.x4.shared.b16 {%0,%1,%2,%3}, [%4];" \
               : "=r"(r0), "=r"(r1), "=r"(r2), "=r"(r3) : "r"(addr))
#define MMA16816(c0,c1,c2,c3,a0,a1,a2,a3,b0,b1) \
  asm volatile("mma.sync.aligned.m16n8k16.row.col.f32.bf16.bf16.f32 " \
               "{%0,%1,%2,%3}, {%4,%5,%6,%7}, {%8,%9}, {%0,%1,%2,%3};" \
               : "+f"(c0), "+f"(c1), "+f"(c2), "+f"(c3) \
               : "r"(a0), "r"(a1), "r"(a2), "r"(a3), "r"(b0), "r"(b1))

template<int MODE>
__global__ __launch_bounds__(256) void k_gemm() {
  constexpr int KF = MODE ? 3072 : 6144;
  constexpr int KT = KF / 64;            // tiles per split-K half
  const __nv_bfloat16* __restrict__ A  = MODE ? g_Al : g_Ag;
  const __nv_bfloat16* __restrict__ Bt = MODE ? g_Wo : g_Wg;

  __shared__ __nv_bfloat16 sm[2 * 2 * 128 * 40];   // [stage][A|B][128][40]
  const uint32_t sbase = smem_to_u32(sm);

  const int tid = threadIdx.x;
  const int l = tid & 31, w = tid >> 5;
  const int wm = (w & 1) * 64, wn = (w >> 1) * 32;
  const int m0 = blockIdx.y * 128, n0 = blockIdx.x * 128;
  const int kbase = blockIdx.z * (KF / 2);
  float* __restrict__ out = &g_part[blockIdx.z][0];

  float acc[4][4][4];
#pragma unroll
  for (int a = 0; a < 4; a++)
#pragma unroll
    for (int b = 0; b < 4; b++)
#pragma unroll
      for (int c = 0; c < 4; c++) acc[a][b][c] = 0.f;

  const int lr = tid >> 2, lc = (tid & 3) * 8;

#define LOAD_STAGE(st, kt) do {                                               \
    int kk_ = kbase + (kt) * 32;                                              \
    _Pragma("unroll")                                                         \
    for (int i_ = 0; i_ < 2; i_++) {                                          \
      int r_ = lr + i_ * 64;                                                  \
      uint32_t da_ = sbase + (st) * 20480 + (r_ * 40 + lc) * 2;               \
      const __nv_bfloat16* ga_ = A + (size_t)(m0 + r_) * KF + kk_ + lc;       \
      asm volatile("cp.async.cg.shared.global [%0], [%1], 16;"                \
                   :: "r"(da_), "l"(ga_));                                    \
      uint32_t db_ = da_ + 10240;                                             \
      const __nv_bfloat16* gb_ = Bt + (size_t)(n0 + r_) * KF + kk_ + lc;      \
      asm volatile("cp.async.cg.shared.global [%0], [%1], 16;"                \
                   :: "r"(db_), "l"(gb_));                                    \
    }                                                                         \
    asm volatile("cp.async.commit_group;");                                   \
  } while (0)

  LOAD_STAGE(0, 0);

  for (int kt = 0; kt < KT; kt++) {
    if (kt + 1 < KT) {
      LOAD_STAGE((kt + 1) & 1, kt + 1);
      asm volatile("cp.async.wait_group 1;");
    } else {
      asm volatile("cp.async.wait_group 0;");
    }
    __syncthreads();

    const uint32_t abase = sbase + (kt & 1) * 20480;
    const uint32_t bbase = abase + 10240;
#pragma unroll
    for (int kk = 0; kk < 32; kk += 16) {
      uint32_t af[4][4];
#pragma unroll
      for (int fm = 0; fm < 4; fm++) {
        int row = wm + fm * 16 + (l & 15);
        int col = kk + (l >> 4) * 8;
        LDM_X4(af[fm][0], af[fm][1], af[fm][2], af[fm][3],
               abase + (row * 40 + col) * 2);
      }
      uint32_t bf[2][4];
#pragma unroll
      for (int f2 = 0; f2 < 2; f2++) {
        int row = wn + f2 * 16 + ((l >> 4) << 3) + (l & 7);
        int col = kk + ((l >> 3) & 1) * 8;
        LDM_X4(bf[f2][0], bf[f2][1], bf[f2][2], bf[f2][3],
               bbase + (row * 40 + col) * 2);
      }
#pragma unroll
      for (int fm = 0; fm < 4; fm++)
#pragma unroll
        for (int fn = 0; fn < 4; fn++) {
          uint32_t b0 = bf[fn >> 1][(fn & 1) * 2];
          uint32_t b1 = bf[fn >> 1][(fn & 1) * 2 + 1];
          MMA16816(acc[fm][fn][0], acc[fm][fn][1], acc[fm][fn][2], acc[fm][fn][3],
                   af[fm][0], af[fm][1], af[fm][2], af[fm][3], b0, b1);
        }
    }
    __syncthreads();
  }
#undef LOAD_STAGE

#pragma unroll
  for (int fm = 0; fm < 4; fm++)
#pragma unroll
    for (int fn = 0; fn < 4; fn++) {
      int r = m0 + wm + fm * 16 + (l >> 2);
      int c = n0 + wn + fn * 8 + (l & 3) * 2;
      float2 v0 = make_float2(acc[fm][fn][0], acc[fm][fn][1]);
      float2 v1 = make_float2(acc[fm][fn][2], acc[fm][fn][3]);
      *(float2*)&out[(size_t)r * 2048 + c] = v0;
      *(float2*)&out[(size_t)(r + 8) * 2048 + c] = v1;
    }
}

// ---------------------------------------------------------------------------
// LSTM pointwise: combine split-K partials, update c, write h planes into
// gates-A (next step) and logits-A (this step). 512 blocks x 512 threads.
// ---------------------------------------------------------------------------
__global__ __launch_bounds__(512) void k_lstm(const float* __restrict__ b_ih,
                                              const float* __restrict__ b_hh) {
  const int b = blockIdx.x, h = threadIdx.x;
  const int hg = h >> 5, hl = h & 31;
  float gate[4];
#pragma unroll
  for (int g = 0; g < 4; g++) {
    int nn = hg * 128 + g * 32 + hl;
    gate[g] = g_part[0][(size_t)b * 2048 + nn] + g_part[1][(size_t)b * 2048 + nn]
            + b_ih[g * 512 + h] + b_hh[g * 512 + h];
  }
  float cv = g_c[b * 512 + h];
  float cn = sigf(gate[1]) * cv + sigf(gate[0]) * tanhf(gate[2]);
  float hn = sigf(gate[3]) * tanhf(cn);
  g_c[b * 512 + h] = cn;
  __nv_bfloat16 p0, p1, p2; split3(hn, p0, p1, p2);
  __nv_bfloat16 pl[3] = {p0, p1, p2};
  const int PI[6] = {0, 0, 1, 0, 2, 1};
#pragma unroll
  for (int s = 0; s < 6; s++) {
    g_Ag[(size_t)b * 6144 + s * 1024 + 512 + h] = pl[PI[s]];
    g_Al[(size_t)b * 3072 + s * 512 + h]        = pl[PI[s]];
  }
}

// ---------------------------------------------------------------------------
// Sampler: combine logits partials + bias, log-softmax, probs/entropy,
// Gumbel-argmax (JAX partitionable threefry), embedding gather.
// ---------------------------------------------------------------------------
__global__ __launch_bounds__(256) void k_sample(const float* __restrict__ ob,
                                                float* __restrict__ out, int t) {
  const int b = blockIdx.x;
  const int tid = threadIdx.x;
  const float* __restrict__ p0 = &g_part[0][(size_t)b * VV];
  const float* __restrict__ p1 = &g_part[1][(size_t)b * VV];

  float zv[8];
#pragma unroll
  for (int j = 0; j < 8; j++) {
    int v = tid + j * 256;
    zv[j] = p0[v] + p1[v] + ob[v];
  }

  __shared__ float red[256];
  __shared__ float rv[256];
  __shared__ int   ri[256];
  __shared__ int   s_sym;

  float m = zv[0];
#pragma unroll
  for (int j = 1; j < 8; j++) m = fmaxf(m, zv[j]);
  red[tid] = m; __syncthreads();
  for (int s = 128; s > 0; s >>= 1) {
    if (tid < s) red[tid] = fmaxf(red[tid], red[tid + s]);
    __syncthreads();
  }
  const float M = red[0]; __syncthreads();

  float ssum = 0.f;
#pragma unroll
  for (int j = 0; j < 8; j++) ssum += expf(zv[j] - M);
  red[tid] = ssum; __syncthreads();
  for (int s = 128; s > 0; s >>= 1) {
    if (tid < s) red[tid] += red[tid + s];
    __syncthreads();
  }
  const float lse = logf(red[0]); __syncthreads();

  // key chain: key0=(0,1); per step: new_key=tf(key,(0,0)), subkey=tf(key,(0,1))
  uint32_t k0 = 0u, k1 = 1u, sk0 = 0u, sk1 = 0u;
  for (int st = 0; st <= t; st++) {
    uint32_t n0, n1, s0, s1;
    tf2x32(k0, k1, 0u, 0u, n0, n1);
    tf2x32(k0, k1, 0u, 1u, s0, s1);
    sk0 = s0; sk1 = s1; k0 = n0; k1 = n1;
  }

  float entp = 0.f;
  float bestv = -INFINITY;
  int   besti = VV;
  const size_t probs_row = (size_t)PROBS_OFF + ((size_t)b * LP1 + t) * VV;
#pragma unroll
  for (int j = 0; j < 8; j++) {
    int v = tid + j * 256;
    float lsm = zv[j] - M - lse;
    float pr = expf(lsm);
    out[probs_row + v] = pr;
    entp += pr * lsm;
    uint32_t o0, o1;
    tf2x32(sk0, sk1, 0u, (uint32_t)(b * VV + v), o0, o1);
    uint32_t bits = o0 ^ o1;
    float f = __uint_as_float((bits >> 9) | 0x3f800000u) - 1.0f;
    float u = fmaxf(f, 1.1754943508222875e-38f);
    float gum = -logf(-logf(u));
    float val = gum + lsm;
    if (val > bestv || (val == bestv && v < besti)) { bestv = val; besti = v; }
  }

  red[tid] = entp; __syncthreads();
  for (int s = 128; s > 0; s >>= 1) {
    if (tid < s) red[tid] += red[tid + s];
    __syncthreads();
  }
  const float ENT = red[0]; __syncthreads();

  rv[tid] = bestv; ri[tid] = besti; __syncthreads();
  for (int s = 128; s > 0; s >>= 1) {
    if (tid < s) {
      if (rv[tid + s] > rv[tid] ||
          (rv[tid + s] == rv[tid] && ri[tid + s] < ri[tid])) {
        rv[tid] = rv[tid + s]; ri[tid] = ri[tid + s];
      }
    }
    __syncthreads();
  }
  if (tid == 0) {
    int sym = ri[0];
    s_sym = sym;
    out[SEQ_OFF  + b * LP1 + t] = (float)sym;
    out[LOGP_OFF + b * LP1 + t] = (p0[sym] + p1[sym] + ob[sym]) - M - lse;
    out[ENT_OFF  + b * LP1 + t] = -ENT;
  }
  __syncthreads();
  const int sym = s_sym;
  // gather embedding planes (6 segments of 512 bf16 = 256 u32 each)
  const uint32_t* src = (const uint32_t*)&g_E6[(size_t)sym * 3072];
  uint32_t* dst = (uint32_t*)&g_Ag[(size_t)b * 6144];
#pragma unroll
  for (int s = 0; s < 6; s++)
    dst[s * 512 + tid] = src[s * 256 + tid];
}

// ---------------------------------------------------------------------------
extern "C" void kernel_launch(void* const* d_in, const int* in_sizes, int n_in,
                              void* d_out, int out_size) {
  const float* x       = (const float*)d_in[0];
  const float* agent_w = (const float*)d_in[1];
  const float* agent_b = (const float*)d_in[2];
  const float* sos     = (const float*)d_in[3];
  const float* emb     = (const float*)d_in[4];
  const float* w_ih    = (const float*)d_in[5];
  const float* w_hh    = (const float*)d_in[6];
  const float* b_ih    = (const float*)d_in[7];
  const float* b_hh    = (const float*)d_in[8];
  const float* out_w   = (const float*)d_in[9];
  const float* out_b   = (const float*)d_in[10];
  float* out = (float*)d_out;

  k_init<<<4096, 256>>>(sos, out);
  k_split_emb<<<4096, 256>>>(emb);
  k_split_wg<<<dim3(64, 32), 256>>>(w_ih, w_hh);
  k_split_wo<<<dim3(64, 16), 256>>>(out_w);
  k_h0<<<dim3(8, 8), 256>>>(x, agent_w, agent_b);
  k_splitH0<<<1024, 256>>>();

  for (int t = 0; t < 32; t++) {
    k_gemm<0><<<dim3(16, 4, 2), 256>>>();   // gates partials
    k_lstm<<<512, 512>>>(b_ih, b_hh);       // LSTM + write h planes
    k_gemm<1><<<dim3(16, 4, 2), 256>>>();   // logits partials
    k_sample<<<512, 256>>>(out_b, out, t);  // softmax/sample/gather
  }
}